// round 5
// baseline (speedup 1.0000x reference)
#include <cuda_runtime.h>
#include <cuda_bf16.h>
#include <cstdint>

// Block-causal attention, mma.sync split-bf16 (3 MMAs/GEMM, fp32 accuracy).
// 512-thread CTAs (4 warps/SMSP for latency hiding), warp-group split:
//   wg0: GEMM1 s-cols 0-31, GEMM2 out v-cols 0-31;  wg1: the other halves.
// P exchanged via smem (bf16 hi/lo, ldmatrix A-fragment layout).
// Split-K over s-tiles (z=2) + additive combine (no-max softmax).

#define SEQ 2048
#define DH  64
#define QT  128
#define ST  64
#define PITCHB 144

#define SM_QHI 0
#define SM_QLO (SM_QHI + 128 * PITCHB)   // 18432
#define SM_KHI (SM_QLO + 128 * PITCHB)   // 36864
#define SM_KLO (SM_KHI + 64 * PITCHB)    // 46080
#define SM_VHI (SM_KLO + 64 * PITCHB)    // 55296
#define SM_VLO (SM_VHI + 64 * PITCHB)    // 64512
#define SM_PHI (SM_VLO + 64 * PITCHB)    // 73728
#define SM_PLO (SM_PHI + 128 * PITCHB)   // 92160
#define SM_LRED (SM_PLO + 128 * PITCHB)  // 110592
#define SM_TOTAL (SM_LRED + 1024)        // 111616

__device__ float g_scr[2][8 * SEQ * DH];
__device__ float g_l[2][8 * SEQ];

__device__ __forceinline__ uint32_t smem_u32(const void* p) {
    uint32_t a;
    asm("{ .reg .u64 t; cvta.to.shared.u64 t, %1; cvt.u32.u64 %0, t; }"
        : "=r"(a) : "l"(p));
    return a;
}
#define LDSM_X4(r, a) \
    asm volatile("ldmatrix.sync.aligned.m8n8.x4.shared.b16 {%0,%1,%2,%3}, [%4];" \
        : "=r"((r)[0]), "=r"((r)[1]), "=r"((r)[2]), "=r"((r)[3]) : "r"(a))

__device__ __forceinline__ void mma_bf16(float* c, const uint32_t* a, const uint32_t* b) {
    asm volatile(
        "mma.sync.aligned.m16n8k16.row.col.f32.bf16.bf16.f32 "
        "{%0,%1,%2,%3}, {%4,%5,%6,%7}, {%8,%9}, {%0,%1,%2,%3};"
        : "+f"(c[0]), "+f"(c[1]), "+f"(c[2]), "+f"(c[3])
        : "r"(a[0]), "r"(a[1]), "r"(a[2]), "r"(a[3]), "r"(b[0]), "r"(b[1]));
}
__device__ __forceinline__ uint32_t packbf(__nv_bfloat16 a, __nv_bfloat16 b) {
    __nv_bfloat162 t; t.x = a; t.y = b;
    return *reinterpret_cast<uint32_t*>(&t);
}
__device__ __forceinline__ void split8(const float* x, uint4& hi, uint4& lo) {
    uint32_t h[4], l[4];
#pragma unroll
    for (int m = 0; m < 4; m++) {
        float a = x[2 * m], b = x[2 * m + 1];
        __nv_bfloat16 ha = __float2bfloat16_rn(a), hb = __float2bfloat16_rn(b);
        h[m] = packbf(ha, hb);
        l[m] = packbf(__float2bfloat16_rn(a - __bfloat162float(ha)),
                      __float2bfloat16_rn(b - __bfloat162float(hb)));
    }
    hi = make_uint4(h[0], h[1], h[2], h[3]);
    lo = make_uint4(l[0], l[1], l[2], l[3]);
}
__device__ __forceinline__ void split2(float a, float b, uint32_t& h, uint32_t& l) {
    __nv_bfloat16 ha = __float2bfloat16_rn(a), hb = __float2bfloat16_rn(b);
    h = packbf(ha, hb);
    l = packbf(__float2bfloat16_rn(a - __bfloat162float(ha)),
               __float2bfloat16_rn(b - __bfloat162float(hb)));
}

__global__ __launch_bounds__(512, 1)
void attn_part_kernel(const float* __restrict__ Q, const float* __restrict__ K,
                      const float* __restrict__ V, const int* __restrict__ prefix) {
    extern __shared__ char smem[];
    const uint32_t sb = smem_u32(smem);
    const int tid  = threadIdx.x;
    const int lane = tid & 31;
    const int w    = tid >> 5;
    const int wg   = w >> 3;          // warp group 0/1
    const int ws   = w & 7;           // q-row slice within the group
    const int tg   = lane & 3;
    const int g    = lane >> 2;
    const int n    = blockIdx.y;
    const int qb   = blockIdx.x;
    const int sp   = blockIdx.z;
    const int q0   = qb * QT;
    const int P    = prefix[n];
    const int m0   = ws * 16;
    const int c0   = wg * 32;         // this group's s-col / v-col base

    // ---- Q tile -> smem hi/lo (512 threads: 16 floats each) ----
    {
        const int r = tid >> 2, dbase = (tid & 3) * 16;
#pragma unroll
        for (int h = 0; h < 2; h++) {
            const int d = dbase + h * 8;
            float x[8];
            const float* qp = Q + (size_t)(n * SEQ + q0 + r) * DH + d;
            *(float4*)&x[0] = *(const float4*)qp;
            *(float4*)&x[4] = *(const float4*)(qp + 4);
            uint4 hi, lo; split8(x, hi, lo);
            *(uint4*)(smem + SM_QHI + r * PITCHB + d * 2) = hi;
            *(uint4*)(smem + SM_QLO + r * PITCHB + d * 2) = lo;
        }
    }
    __syncthreads();

    // ---- Q A-fragments in registers ----
    uint32_t qh[4][4], ql[4][4];
    {
        const uint32_t abase = sb + (m0 + (lane & 15)) * PITCHB + ((lane >> 4) & 1) * 16;
#pragma unroll
        for (int kk = 0; kk < 4; kk++) {
            LDSM_X4(qh[kk], abase + SM_QHI + kk * 32);
            LDSM_X4(ql[kk], abase + SM_QLO + kk * 32);
        }
    }

    float oacc[4][4];
#pragma unroll
    for (int j = 0; j < 4; j++)
#pragma unroll
        for (int e = 0; e < 4; e++) oacc[j][e] = 0.0f;
    float ls0 = 0.0f, ls1 = 0.0f;

    // ---- owned tile schedule (split sp owns prefix tiles t%2==sp + its diag) ----
    const int T = (P + ST - 1) / ST;
    const int diagT = qb * 2 + sp;
    const int nPref = (T > sp) ? ((T - sp + 1) >> 1) : 0;
    const int nIter = nPref + (diagT >= T ? 1 : 0);
    auto tile_of = [&](int it) -> int {
        return (it < nPref) ? (2 * it + sp) : diagT;
    };

    // ---- prefetch tile 0 (K: 8 floats/thread, Vt: 8 gathers/thread) ----
    const int kr = tid >> 3, kd = (tid & 7) * 8;
    const int vv = tid & 63, vs8 = (tid >> 6) * 8;
    float kx[8], vx[8];
    {
        const int s0n = tile_of(0) * ST;
        const float* kp = K + (size_t)(n * SEQ + s0n + kr) * DH + kd;
        *(float4*)&kx[0] = *(const float4*)kp;
        *(float4*)&kx[4] = *(const float4*)(kp + 4);
#pragma unroll
        for (int k = 0; k < 8; k++)
            vx[k] = V[(size_t)(n * SEQ + s0n + vs8 + k) * DH + vv];
    }

    // fragment address bases
    const uint32_t rowfrag = (lane & 7) + ((lane >> 4) & 1) * 8;   // B-frag row-in-16
    const uint32_t khalf   = ((lane >> 3) & 1) * 16;               // B-frag k-half bytes
    const uint32_t bK = sb + SM_KHI + (c0 + rowfrag) * PITCHB + khalf;
    const uint32_t bV = sb + SM_VHI + (c0 + rowfrag) * PITCHB + khalf;
    const uint32_t aP = sb + SM_PHI + (m0 + (lane & 15)) * PITCHB + ((lane >> 4) & 1) * 16;

    for (int it = 0; it < nIter; ++it) {
        const int s0 = tile_of(it) * ST;

        __syncthreads();                       // everyone done with prev K/V/P
        {
            uint4 hi, lo;
            split8(kx, hi, lo);
            *(uint4*)(smem + SM_KHI + kr * PITCHB + kd * 2) = hi;
            *(uint4*)(smem + SM_KLO + kr * PITCHB + kd * 2) = lo;
            split8(vx, hi, lo);
            *(uint4*)(smem + SM_VHI + vv * PITCHB + vs8 * 2) = hi;
            *(uint4*)(smem + SM_VLO + vv * PITCHB + vs8 * 2) = lo;
        }
        __syncthreads();

        if (it + 1 < nIter) {                  // prefetch next tile
            const int s0n = tile_of(it + 1) * ST;
            const float* kp = K + (size_t)(n * SEQ + s0n + kr) * DH + kd;
            *(float4*)&kx[0] = *(const float4*)kp;
            *(float4*)&kx[4] = *(const float4*)(kp + 4);
#pragma unroll
            for (int k = 0; k < 8; k++)
                vx[k] = V[(size_t)(n * SEQ + s0n + vs8 + k) * DH + vv];
        }

        // ---- GEMM1: sc = Q @ K^T for this group's 32 s-cols ----
        float sc[4][4];
#pragma unroll
        for (int j = 0; j < 4; j++)
#pragma unroll
            for (int e = 0; e < 4; e++) sc[j][e] = 0.0f;
#pragma unroll
        for (int jp = 0; jp < 2; jp++) {
            const uint32_t ka = bK + jp * (16 * PITCHB);
#pragma unroll
            for (int kk = 0; kk < 4; kk++) {
                uint32_t bh[4], bl[4];
                LDSM_X4(bh, ka + kk * 32);
                LDSM_X4(bl, ka + (SM_KLO - SM_KHI) + kk * 32);
                mma_bf16(sc[2 * jp],     qh[kk], bh);
                mma_bf16(sc[2 * jp],     qh[kk], bl);
                mma_bf16(sc[2 * jp],     ql[kk], bh);
                mma_bf16(sc[2 * jp + 1], qh[kk], bh + 2);
                mma_bf16(sc[2 * jp + 1], qh[kk], bl + 2);
                mma_bf16(sc[2 * jp + 1], ql[kk], bh + 2);
            }
        }

        // ---- mask + exp ----
        const int row0 = q0 + m0 + g;
        const int row1 = row0 + 8;
#pragma unroll
        for (int j = 0; j < 4; j++) {
            const int cb = s0 + c0 + j * 8 + tg * 2;
#pragma unroll
            for (int e = 0; e < 2; e++) {
                const int cc = cb + e;
                const float pa = ((cc < P) || (cc == row0))
                                 ? __expf(sc[j][e] * 0.125f) : 0.0f;
                const float pb = ((cc < P) || (cc == row1))
                                 ? __expf(sc[j][2 + e] * 0.125f) : 0.0f;
                sc[j][e] = pa;     ls0 += pa;
                sc[j][2 + e] = pb; ls1 += pb;
            }
        }

        // ---- store P hi/lo to smem (ldmatrix-ready layout) ----
#pragma unroll
        for (int j = 0; j < 4; j++) {
            uint32_t ph, pl;
            const uint32_t colb = (c0 + j * 8 + tg * 2) * 2;
            split2(sc[j][0], sc[j][1], ph, pl);
            *(uint32_t*)(smem + SM_PHI + (m0 + g) * PITCHB + colb) = ph;
            *(uint32_t*)(smem + SM_PLO + (m0 + g) * PITCHB + colb) = pl;
            split2(sc[j][2], sc[j][3], ph, pl);
            *(uint32_t*)(smem + SM_PHI + (m0 + g + 8) * PITCHB + colb) = ph;
            *(uint32_t*)(smem + SM_PLO + (m0 + g + 8) * PITCHB + colb) = pl;
        }
        __syncthreads();                       // P visible to both groups

        // ---- GEMM2: oacc += P(full s=64) @ V for this group's 32 v-cols ----
#pragma unroll
        for (int kb = 0; kb < 4; kb++) {
            uint32_t ah[4], al[4];
            LDSM_X4(ah, aP + kb * 32);
            LDSM_X4(al, aP + (SM_PLO - SM_PHI) + kb * 32);
#pragma unroll
            for (int jp = 0; jp < 2; jp++) {
                const uint32_t va = bV + jp * (16 * PITCHB) + kb * 32;
                uint32_t vh[4], vl[4];
                LDSM_X4(vh, va);
                LDSM_X4(vl, va + (SM_VLO - SM_VHI));
                mma_bf16(oacc[2 * jp],     ah, vh);
                mma_bf16(oacc[2 * jp],     ah, vl);
                mma_bf16(oacc[2 * jp],     al, vh);
                mma_bf16(oacc[2 * jp + 1], ah, vh + 2);
                mma_bf16(oacc[2 * jp + 1], ah, vl + 2);
                mma_bf16(oacc[2 * jp + 1], al, vh + 2);
            }
        }
    }

    // ---- epilogue: l reduce (tg lanes, then across warp groups via smem) ----
    ls0 += __shfl_xor_sync(0xffffffffu, ls0, 1);
    ls0 += __shfl_xor_sync(0xffffffffu, ls0, 2);
    ls1 += __shfl_xor_sync(0xffffffffu, ls1, 1);
    ls1 += __shfl_xor_sync(0xffffffffu, ls1, 2);

    float* lred = (float*)(smem + SM_LRED);
    const int row0 = q0 + m0 + g;
    const int row1 = row0 + 8;
    if (tg == 0) {
        lred[wg * 128 + m0 + g]     = ls0;
        lred[wg * 128 + m0 + g + 8] = ls1;
    }
    __syncthreads();
    if (wg == 0 && tg == 0) {
        g_l[sp][n * SEQ + row0] = lred[m0 + g]     + lred[128 + m0 + g];
        g_l[sp][n * SEQ + row1] = lred[m0 + g + 8] + lred[128 + m0 + g + 8];
    }

    float* scr = g_scr[sp];
#pragma unroll
    for (int j = 0; j < 4; j++) {
        const int col = c0 + j * 8 + tg * 2;
        *(float2*)(scr + (size_t)(n * SEQ + row0) * DH + col) =
            make_float2(oacc[j][0], oacc[j][1]);
        *(float2*)(scr + (size_t)(n * SEQ + row1) * DH + col) =
            make_float2(oacc[j][2], oacc[j][3]);
    }
}

__global__ __launch_bounds__(256, 8)
void combine_kernel(float* __restrict__ O) {
    const int i = blockIdx.x * 256 + threadIdx.x;
    const int row = i >> 4;
    const float4 a = ((const float4*)g_scr[0])[i];
    const float4 b = ((const float4*)g_scr[1])[i];
    const float inv = 1.0f / (g_l[0][row] + g_l[1][row]);
    ((float4*)O)[i] = make_float4((a.x + b.x) * inv, (a.y + b.y) * inv,
                                  (a.z + b.z) * inv, (a.w + b.w) * inv);
}

extern "C" void kernel_launch(void* const* d_in, const int* in_sizes, int n_in,
                              void* d_out, int out_size) {
    const float* Q      = (const float*)d_in[0];
    const float* K      = (const float*)d_in[1];
    const float* V      = (const float*)d_in[2];
    const int*   prefix = (const int*)d_in[3];
    float*       O      = (float*)d_out;

    cudaFuncSetAttribute(attn_part_kernel,
                         cudaFuncAttributeMaxDynamicSharedMemorySize, SM_TOTAL);
    attn_part_kernel<<<dim3(16, 8, 2), 512, SM_TOTAL>>>(Q, K, V, prefix);
    combine_kernel<<<(8 * SEQ * DH / 4) / 256, 256>>>(O);
}

// round 6
// speedup vs baseline: 1.7863x; 1.7863x over previous
#include <cuda_runtime.h>
#include <cuda_fp16.h>
#include <cstdint>

// Block-causal attention, mma.sync fp16: A-operand split hi/lo (2 MMAs),
// B-operand single fp16 (11-bit mantissa => ~2e-4 output rel err).
// Round-4 structure (256 thr, P in registers), KSPLIT=4 + additive combine.

#define SEQ 2048
#define DH  64
#define QT  128
#define ST  64
#define PITCHB 144
#define KS  4

#define SM_QHI 0
#define SM_QLO (SM_QHI + 128 * PITCHB)   // 18432
#define SM_K   (SM_QLO + 128 * PITCHB)   // 36864
#define SM_V   (SM_K + 64 * PITCHB)      // 46080
#define SM_TOTAL (SM_V + 64 * PITCHB)    // 55296

__device__ float g_scr[KS][8 * SEQ * DH];   // 16 MB partials
__device__ float g_l[KS][8 * SEQ];

__device__ __forceinline__ uint32_t smem_u32(const void* p) {
    uint32_t a;
    asm("{ .reg .u64 t; cvta.to.shared.u64 t, %1; cvt.u32.u64 %0, t; }"
        : "=r"(a) : "l"(p));
    return a;
}
#define LDSM_X4(r, a) \
    asm volatile("ldmatrix.sync.aligned.m8n8.x4.shared.b16 {%0,%1,%2,%3}, [%4];" \
        : "=r"((r)[0]), "=r"((r)[1]), "=r"((r)[2]), "=r"((r)[3]) : "r"(a))

__device__ __forceinline__ void mma_f16(float* c, const uint32_t* a, const uint32_t* b) {
    asm volatile(
        "mma.sync.aligned.m16n8k16.row.col.f32.f16.f16.f32 "
        "{%0,%1,%2,%3}, {%4,%5,%6,%7}, {%8,%9}, {%0,%1,%2,%3};"
        : "+f"(c[0]), "+f"(c[1]), "+f"(c[2]), "+f"(c[3])
        : "r"(a[0]), "r"(a[1]), "r"(a[2]), "r"(a[3]), "r"(b[0]), "r"(b[1]));
}
__device__ __forceinline__ uint32_t packh(__half a, __half b) {
    __half2 t; t.x = a; t.y = b;
    return *reinterpret_cast<uint32_t*>(&t);
}
__device__ __forceinline__ void split8h(const float* x, uint4& hi, uint4& lo) {
    uint32_t h[4], l[4];
#pragma unroll
    for (int m = 0; m < 4; m++) {
        float a = x[2 * m], b = x[2 * m + 1];
        __half ha = __float2half_rn(a), hb = __float2half_rn(b);
        h[m] = packh(ha, hb);
        l[m] = packh(__float2half_rn(a - __half2float(ha)),
                     __float2half_rn(b - __half2float(hb)));
    }
    hi = make_uint4(h[0], h[1], h[2], h[3]);
    lo = make_uint4(l[0], l[1], l[2], l[3]);
}
__device__ __forceinline__ uint4 cvt8h(const float* x) {
    uint32_t h[4];
#pragma unroll
    for (int m = 0; m < 4; m++)
        h[m] = packh(__float2half_rn(x[2 * m]), __float2half_rn(x[2 * m + 1]));
    return make_uint4(h[0], h[1], h[2], h[3]);
}
__device__ __forceinline__ void split2h(float a, float b, uint32_t& h, uint32_t& l) {
    __half ha = __float2half_rn(a), hb = __float2half_rn(b);
    h = packh(ha, hb);
    l = packh(__float2half_rn(a - __half2float(ha)),
              __float2half_rn(b - __half2float(hb)));
}

__global__ __launch_bounds__(256, 1)
void attn_part_kernel(const float* __restrict__ Q, const float* __restrict__ K,
                      const float* __restrict__ V, const int* __restrict__ prefix) {
    extern __shared__ char smem[];
    const uint32_t sb = smem_u32(smem);
    const int tid  = threadIdx.x;
    const int lane = tid & 31;
    const int w    = tid >> 5;
    const int tg   = lane & 3;
    const int g    = lane >> 2;
    const int n    = blockIdx.y;
    const int qb   = blockIdx.x;
    const int sp   = blockIdx.z;
    const int q0   = qb * QT;
    const int P    = prefix[n];
    const int m0   = w * 16;

    // ---- Q tile -> smem hi/lo ----
#pragma unroll
    for (int gi = 0; gi < 4; gi++) {
        const int gg = tid + 256 * gi;
        const int r = gg >> 3, d8 = (gg & 7) * 8;
        float x[8];
        const float* qp = Q + (size_t)(n * SEQ + q0 + r) * DH + d8;
        *(float4*)&x[0] = *(const float4*)qp;
        *(float4*)&x[4] = *(const float4*)(qp + 4);
        uint4 hi, lo; split8h(x, hi, lo);
        *(uint4*)(smem + SM_QHI + r * PITCHB + d8 * 2) = hi;
        *(uint4*)(smem + SM_QLO + r * PITCHB + d8 * 2) = lo;
    }
    __syncthreads();

    // ---- Q A-fragments (registers, whole kernel) ----
    uint32_t qh[4][4], ql[4][4];
    {
        const uint32_t abase = sb + (m0 + (lane & 15)) * PITCHB + ((lane >> 4) & 1) * 16;
#pragma unroll
        for (int kk = 0; kk < 4; kk++) {
            LDSM_X4(qh[kk], abase + SM_QHI + kk * 32);
            LDSM_X4(ql[kk], abase + SM_QLO + kk * 32);
        }
    }

    float oacc[8][4];
#pragma unroll
    for (int j = 0; j < 8; j++)
#pragma unroll
        for (int e = 0; e < 4; e++) oacc[j][e] = 0.0f;
    float ls0 = 0.0f, ls1 = 0.0f;

    // ---- tile schedule: prefix tiles t%KS==sp, + diag tiles (mod-matched) ----
    const int T = (P + ST - 1) / ST;
    const int dA = qb * 2, dB = qb * 2 + 1;
    const int nPref = (T > sp) ? ((T - sp + 3) >> 2) : 0;
    const bool hasA = (dA >= T) && ((dA & (KS - 1)) == sp);
    const bool hasB = (dB >= T) && ((dB & (KS - 1)) == sp);
    const int nIter = nPref + (hasA ? 1 : 0) + (hasB ? 1 : 0);

    auto tile_of = [&](int it) -> int {
        if (it < nPref) return KS * it + sp;
        if (hasA && it == nPref) return dA;
        return dB;
    };

    const uint32_t boff =
        ((((lane >> 4) & 1) * 8 + (lane & 7)) * PITCHB) + ((lane >> 3) & 1) * 16;
    const uint32_t bK = sb + SM_K + boff;
    const uint32_t bV = sb + SM_V + boff;

    // ---- prefetch tile 0 ----
    float kx[2][8], vx[2][8];
    if (nIter > 0) {
        const int s0n = tile_of(0) * ST;
#pragma unroll
        for (int gi = 0; gi < 2; gi++) {
            const int gg = tid + 256 * gi;
            const int kr = gg >> 3, kd = (gg & 7) * 8;
            const float* kp = K + (size_t)(n * SEQ + s0n + kr) * DH + kd;
            *(float4*)&kx[gi][0] = *(const float4*)kp;
            *(float4*)&kx[gi][4] = *(const float4*)(kp + 4);
            const int vv = gg & 63, vs8 = (gg >> 6) * 8;
#pragma unroll
            for (int k = 0; k < 8; k++)
                vx[gi][k] = V[(size_t)(n * SEQ + s0n + vs8 + k) * DH + vv];
        }
    }

    for (int it = 0; it < nIter; ++it) {
        const int s0 = tile_of(it) * ST;

        __syncthreads();
#pragma unroll
        for (int gi = 0; gi < 2; gi++) {
            const int gg = tid + 256 * gi;
            const int kr = gg >> 3, kd = (gg & 7) * 8;
            *(uint4*)(smem + SM_K + kr * PITCHB + kd * 2) = cvt8h(kx[gi]);
            const int vv = gg & 63, vs8 = (gg >> 6) * 8;
            *(uint4*)(smem + SM_V + vv * PITCHB + vs8 * 2) = cvt8h(vx[gi]);
        }
        __syncthreads();

        if (it + 1 < nIter) {
            const int s0n = tile_of(it + 1) * ST;
#pragma unroll
            for (int gi = 0; gi < 2; gi++) {
                const int gg = tid + 256 * gi;
                const int kr = gg >> 3, kd = (gg & 7) * 8;
                const float* kp = K + (size_t)(n * SEQ + s0n + kr) * DH + kd;
                *(float4*)&kx[gi][0] = *(const float4*)kp;
                *(float4*)&kx[gi][4] = *(const float4*)(kp + 4);
                const int vv = gg & 63, vs8 = (gg >> 6) * 8;
#pragma unroll
                for (int k = 0; k < 8; k++)
                    vx[gi][k] = V[(size_t)(n * SEQ + s0n + vs8 + k) * DH + vv];
            }
        }

        // ---- GEMM1: sc = Q @ K^T (A hi/lo, B single: 2 MMAs) ----
        float sc[8][4];
#pragma unroll
        for (int j = 0; j < 8; j++)
#pragma unroll
            for (int e = 0; e < 4; e++) sc[j][e] = 0.0f;
#pragma unroll
        for (int jp = 0; jp < 4; jp++) {
            const uint32_t ka = bK + jp * (16 * PITCHB);
#pragma unroll
            for (int kk = 0; kk < 4; kk++) {
                uint32_t bh[4];
                LDSM_X4(bh, ka + kk * 32);
                mma_f16(sc[2 * jp],     qh[kk], bh);
                mma_f16(sc[2 * jp],     ql[kk], bh);
                mma_f16(sc[2 * jp + 1], qh[kk], bh + 2);
                mma_f16(sc[2 * jp + 1], ql[kk], bh + 2);
            }
        }

        // ---- mask + exp ----
        const int row0 = q0 + m0 + g;
        const int row1 = row0 + 8;
#pragma unroll
        for (int j = 0; j < 8; j++) {
            const int cb = s0 + j * 8 + tg * 2;
#pragma unroll
            for (int e = 0; e < 2; e++) {
                const int cc = cb + e;
                const float pa = ((cc < P) || (cc == row0))
                                 ? __expf(sc[j][e] * 0.125f) : 0.0f;
                const float pb = ((cc < P) || (cc == row1))
                                 ? __expf(sc[j][2 + e] * 0.125f) : 0.0f;
                sc[j][e] = pa;     ls0 += pa;
                sc[j][2 + e] = pb; ls1 += pb;
            }
        }

        // ---- P -> A-fragments (hi/lo fp16) ----
        uint32_t pah[4][4], pal[4][4];
#pragma unroll
        for (int kb = 0; kb < 4; kb++) {
            const int t0 = 2 * kb, t1 = 2 * kb + 1;
            split2h(sc[t0][0], sc[t0][1], pah[kb][0], pal[kb][0]);
            split2h(sc[t0][2], sc[t0][3], pah[kb][1], pal[kb][1]);
            split2h(sc[t1][0], sc[t1][1], pah[kb][2], pal[kb][2]);
            split2h(sc[t1][2], sc[t1][3], pah[kb][3], pal[kb][3]);
        }

        // ---- GEMM2: O += P @ V (P hi/lo, V single: 2 MMAs) ----
#pragma unroll
        for (int jp = 0; jp < 4; jp++) {
            const uint32_t va = bV + jp * (16 * PITCHB);
#pragma unroll
            for (int kb = 0; kb < 4; kb++) {
                uint32_t vh[4];
                LDSM_X4(vh, va + kb * 32);
                mma_f16(oacc[2 * jp],     pah[kb], vh);
                mma_f16(oacc[2 * jp],     pal[kb], vh);
                mma_f16(oacc[2 * jp + 1], pah[kb], vh + 2);
                mma_f16(oacc[2 * jp + 1], pal[kb], vh + 2);
            }
        }
    }

    // ---- write partials ----
    ls0 += __shfl_xor_sync(0xffffffffu, ls0, 1);
    ls0 += __shfl_xor_sync(0xffffffffu, ls0, 2);
    ls1 += __shfl_xor_sync(0xffffffffu, ls1, 1);
    ls1 += __shfl_xor_sync(0xffffffffu, ls1, 2);

    const int row0 = q0 + m0 + g;
    const int row1 = row0 + 8;
    if (tg == 0) {
        g_l[sp][n * SEQ + row0] = ls0;
        g_l[sp][n * SEQ + row1] = ls1;
    }
    float* scr = g_scr[sp];
#pragma unroll
    for (int j = 0; j < 8; j++) {
        const int col = j * 8 + tg * 2;
        *(float2*)(scr + (size_t)(n * SEQ + row0) * DH + col) =
            make_float2(oacc[j][0], oacc[j][1]);
        *(float2*)(scr + (size_t)(n * SEQ + row1) * DH + col) =
            make_float2(oacc[j][2], oacc[j][3]);
    }
}

__global__ __launch_bounds__(256, 8)
void combine_kernel(float* __restrict__ O) {
    const int i = blockIdx.x * 256 + threadIdx.x;
    const int row = i >> 4;
    float4 a = ((const float4*)g_scr[0])[i];
    float l = g_l[0][row];
#pragma unroll
    for (int s = 1; s < KS; s++) {
        const float4 b = ((const float4*)g_scr[s])[i];
        a.x += b.x; a.y += b.y; a.z += b.z; a.w += b.w;
        l += g_l[s][row];
    }
    const float inv = 1.0f / l;
    ((float4*)O)[i] = make_float4(a.x * inv, a.y * inv, a.z * inv, a.w * inv);
}

extern "C" void kernel_launch(void* const* d_in, const int* in_sizes, int n_in,
                              void* d_out, int out_size) {
    const float* Q      = (const float*)d_in[0];
    const float* K      = (const float*)d_in[1];
    const float* V      = (const float*)d_in[2];
    const int*   prefix = (const int*)d_in[3];
    float*       O      = (float*)d_out;

    cudaFuncSetAttribute(attn_part_kernel,
                         cudaFuncAttributeMaxDynamicSharedMemorySize, SM_TOTAL);
    attn_part_kernel<<<dim3(16, 8, KS), 256, SM_TOTAL>>>(Q, K, V, prefix);
    combine_kernel<<<(8 * SEQ * DH / 4) / 256, 256>>>(O);
}

// round 7
// speedup vs baseline: 2.0361x; 1.1398x over previous
#include <cuda_runtime.h>
#include <cuda_fp16.h>
#include <cstdint>

// Block-causal attention, mma.sync fp16 (all operands single-rounded fp16,
// fp32 accumulate). Softmax via ex2.approx.f16x2 producing P directly in
// fp16 A-fragments. Row-sums l computed by an extra ones-column MMA.
// KSPLIT=4 over s-tiles + additive combine (no-max softmax: scores in ±6).

#define SEQ 2048
#define DH  64
#define QT  128
#define ST  64
#define PITCHB 144
#define KS  4

#define SM_Q   0
#define SM_K   (SM_Q + 128 * PITCHB)     // 18432
#define SM_V   (SM_K + 64 * PITCHB)      // 27648  (72 rows: 64 data + ones + 7 zero)
#define SM_TOTAL (SM_V + 72 * PITCHB)    // 38016

__device__ float g_scr[KS][8 * SEQ * DH];
__device__ float g_l[KS][8 * SEQ];

__device__ __forceinline__ uint32_t smem_u32(const void* p) {
    uint32_t a;
    asm("{ .reg .u64 t; cvta.to.shared.u64 t, %1; cvt.u32.u64 %0, t; }"
        : "=r"(a) : "l"(p));
    return a;
}
#define LDSM_X4(r, a) \
    asm volatile("ldmatrix.sync.aligned.m8n8.x4.shared.b16 {%0,%1,%2,%3}, [%4];" \
        : "=r"((r)[0]), "=r"((r)[1]), "=r"((r)[2]), "=r"((r)[3]) : "r"(a))
#define LDSM_X2(r, a) \
    asm volatile("ldmatrix.sync.aligned.m8n8.x2.shared.b16 {%0,%1}, [%2];" \
        : "=r"((r)[0]), "=r"((r)[1]) : "r"(a))

__device__ __forceinline__ void mma_f16(float* c, const uint32_t* a, const uint32_t* b) {
    asm volatile(
        "mma.sync.aligned.m16n8k16.row.col.f32.f16.f16.f32 "
        "{%0,%1,%2,%3}, {%4,%5,%6,%7}, {%8,%9}, {%0,%1,%2,%3};"
        : "+f"(c[0]), "+f"(c[1]), "+f"(c[2]), "+f"(c[3])
        : "r"(a[0]), "r"(a[1]), "r"(a[2]), "r"(a[3]), "r"(b[0]), "r"(b[1]));
}
__device__ __forceinline__ uint32_t packh(__half a, __half b) {
    __half2 t; t.x = a; t.y = b;
    return *reinterpret_cast<uint32_t*>(&t);
}
__device__ __forceinline__ uint4 cvt8h(const float* x) {
    uint32_t h[4];
#pragma unroll
    for (int m = 0; m < 4; m++)
        h[m] = packh(__float2half_rn(x[2 * m]), __float2half_rn(x[2 * m + 1]));
    return make_uint4(h[0], h[1], h[2], h[3]);
}
// pack two fp32 (lo, hi) -> f16x2 and take ex2
__device__ __forceinline__ uint32_t exp2_pair(float lo, float hi) {
    uint32_t t;
    asm("cvt.rn.f16x2.f32 %0, %1, %2;" : "=r"(t) : "f"(hi), "f"(lo));
    asm("ex2.approx.f16x2 %0, %0;" : "+r"(t));
    return t;
}

__global__ __launch_bounds__(256, 2)
void attn_part_kernel(const float* __restrict__ Q, const float* __restrict__ K,
                      const float* __restrict__ V, const int* __restrict__ prefix) {
    extern __shared__ char smem[];
    const uint32_t sb = smem_u32(smem);
    const int tid  = threadIdx.x;
    const int lane = tid & 31;
    const int w    = tid >> 5;
    const int tg   = lane & 3;
    const int g    = lane >> 2;
    const int n    = blockIdx.y;
    const int qb   = blockIdx.x;
    const int sp   = blockIdx.z;
    const int q0   = qb * QT;
    const int P    = prefix[n];
    const int m0   = w * 16;

    // ---- Q tile -> smem fp16; init ones-row (64) / zero rows (65-71) of Vt ----
#pragma unroll
    for (int gi = 0; gi < 2; gi++) {
        const int gg = tid + 256 * gi;
        const int r = gg >> 2, d8 = (gg & 3) * 16;
        float x[8];
        const float* qp = Q + (size_t)(n * SEQ + q0 + r) * DH + d8;
        *(float4*)&x[0] = *(const float4*)qp;
        *(float4*)&x[4] = *(const float4*)(qp + 4);
        *(uint4*)(smem + SM_Q + r * PITCHB + d8 * 2) = cvt8h(x);
        float y[8];
        *(float4*)&y[0] = *(const float4*)(qp + 8);
        *(float4*)&y[4] = *(const float4*)(qp + 12);
        *(uint4*)(smem + SM_Q + r * PITCHB + d8 * 2 + 16) = cvt8h(y);
    }
    {
        uint32_t* vz = (uint32_t*)(smem + SM_V + 64 * PITCHB);
        for (int i = tid; i < 8 * PITCHB / 4; i += 256) vz[i] = 0;
        __syncthreads();               // also covers Q stores
        if (tid < 32) vz[tid] = 0x3C003C00u;   // row 64 cols 0-63 = fp16 ones
    }
    __syncthreads();

    // ---- Q A-fragments in registers ----
    uint32_t qh[4][4];
    {
        const uint32_t abase = sb + SM_Q + (m0 + (lane & 15)) * PITCHB +
                               ((lane >> 4) & 1) * 16;
#pragma unroll
        for (int kk = 0; kk < 4; kk++) LDSM_X4(qh[kk], abase + kk * 32);
    }

    float oacc[8][4], lacc[4];
#pragma unroll
    for (int j = 0; j < 8; j++)
#pragma unroll
        for (int e = 0; e < 4; e++) oacc[j][e] = 0.0f;
#pragma unroll
    for (int e = 0; e < 4; e++) lacc[e] = 0.0f;

    // ---- tile schedule: prefix tiles t%KS==sp + mod-matched diagonal tiles ----
    const int T = (P + ST - 1) / ST;
    const int dA = qb * 2, dB = qb * 2 + 1;
    const int nPref = (T > sp) ? ((T - sp + 3) >> 2) : 0;
    const bool hasA = (dA >= T) && ((dA & (KS - 1)) == sp);
    const bool hasB = (dB >= T) && ((dB & (KS - 1)) == sp);
    const int nIter = nPref + (hasA ? 1 : 0) + (hasB ? 1 : 0);
    auto tile_of = [&](int it) -> int {
        if (it < nPref) return KS * it + sp;
        if (hasA && it == nPref) return dA;
        return dB;
    };

    const uint32_t boff =
        ((((lane >> 4) & 1) * 8 + (lane & 7)) * PITCHB) + ((lane >> 3) & 1) * 16;
    const uint32_t bK = sb + SM_K + boff;
    const uint32_t bV = sb + SM_V + boff;
    const uint32_t bOnes = sb + SM_V + (64 + (lane & 7)) * PITCHB +
                           ((lane >> 3) & 1) * 16;

    // ---- prefetch tile 0 ----
    float kx[2][8], vx[2][8];
    if (nIter > 0) {
        const int s0n = tile_of(0) * ST;
#pragma unroll
        for (int gi = 0; gi < 2; gi++) {
            const int gg = tid + 256 * gi;
            const int kr = gg >> 3, kd = (gg & 7) * 8;
            const float* kp = K + (size_t)(n * SEQ + s0n + kr) * DH + kd;
            *(float4*)&kx[gi][0] = *(const float4*)kp;
            *(float4*)&kx[gi][4] = *(const float4*)(kp + 4);
            const int vv = gg & 63, vs8 = (gg >> 6) * 8;
#pragma unroll
            for (int k = 0; k < 8; k++)
                vx[gi][k] = V[(size_t)(n * SEQ + s0n + vs8 + k) * DH + vv];
        }
    }

    const float C = 0.18033688011112042f;   // log2(e)/8
    for (int it = 0; it < nIter; ++it) {
        const int s0 = tile_of(it) * ST;

        __syncthreads();
#pragma unroll
        for (int gi = 0; gi < 2; gi++) {
            const int gg = tid + 256 * gi;
            const int kr = gg >> 3, kd = (gg & 7) * 8;
            *(uint4*)(smem + SM_K + kr * PITCHB + kd * 2) = cvt8h(kx[gi]);
            const int vv = gg & 63, vs8 = (gg >> 6) * 8;
            *(uint4*)(smem + SM_V + vv * PITCHB + vs8 * 2) = cvt8h(vx[gi]);
        }
        __syncthreads();

        if (it + 1 < nIter) {
            const int s0n = tile_of(it + 1) * ST;
#pragma unroll
            for (int gi = 0; gi < 2; gi++) {
                const int gg = tid + 256 * gi;
                const int kr = gg >> 3, kd = (gg & 7) * 8;
                const float* kp = K + (size_t)(n * SEQ + s0n + kr) * DH + kd;
                *(float4*)&kx[gi][0] = *(const float4*)kp;
                *(float4*)&kx[gi][4] = *(const float4*)(kp + 4);
                const int vv = gg & 63, vs8 = (gg >> 6) * 8;
#pragma unroll
                for (int k = 0; k < 8; k++)
                    vx[gi][k] = V[(size_t)(n * SEQ + s0n + vs8 + k) * DH + vv];
            }
        }

        // ---- GEMM1: sc = Q @ K^T (single fp16, 1 MMA per step) ----
        float sc[8][4];
#pragma unroll
        for (int j = 0; j < 8; j++)
#pragma unroll
            for (int e = 0; e < 4; e++) sc[j][e] = 0.0f;
#pragma unroll
        for (int jp = 0; jp < 4; jp++) {
            const uint32_t ka = bK + jp * (16 * PITCHB);
#pragma unroll
            for (int kk = 0; kk < 4; kk++) {
                uint32_t bh[4];
                LDSM_X4(bh, ka + kk * 32);
                mma_f16(sc[2 * jp],     qh[kk], bh);
                mma_f16(sc[2 * jp + 1], qh[kk], bh + 2);
            }
        }

        // ---- mask + exp2 -> P fragments (fp16x2, A-fragment-ready) ----
        const int row0 = q0 + m0 + g;
        const int row1 = row0 + 8;
        uint32_t pa[8][2];
#pragma unroll
        for (int j = 0; j < 8; j++) {
            const int cb = s0 + j * 8 + tg * 2;
            const bool ok0 = (cb < P),     okd0 = ok0 || (cb == row0),
                       okd0b = ok0 || (cb == row1);
            const bool ok1 = (cb + 1 < P), okd1 = ok1 || (cb + 1 == row0),
                       okd1b = ok1 || (cb + 1 == row1);
            const float a0 = okd0  ? sc[j][0] * C : -1e30f;
            const float a1 = okd1  ? sc[j][1] * C : -1e30f;
            const float a2 = okd0b ? sc[j][2] * C : -1e30f;
            const float a3 = okd1b ? sc[j][3] * C : -1e30f;
            pa[j][0] = exp2_pair(a0, a1);
            pa[j][1] = exp2_pair(a2, a3);
        }

        // ---- GEMM2: O += P @ V; l += P @ ones ----
#pragma unroll
        for (int kb = 0; kb < 4; kb++) {
            uint32_t af[4] = { pa[2 * kb][0], pa[2 * kb][1],
                               pa[2 * kb + 1][0], pa[2 * kb + 1][1] };
            uint32_t bo[2];
            LDSM_X2(bo, bOnes + kb * 32);
            mma_f16(lacc, af, bo);
#pragma unroll
            for (int jp = 0; jp < 4; jp++) {
                const uint32_t va = bV + jp * (16 * PITCHB) + kb * 32;
                uint32_t vh[4];
                LDSM_X4(vh, va);
                mma_f16(oacc[2 * jp],     af, vh);
                mma_f16(oacc[2 * jp + 1], af, vh + 2);
            }
        }
    }

    // ---- write partials (l sits in lacc[0]/lacc[2] at tg==0 lanes) ----
    const int row0 = q0 + m0 + g;
    const int row1 = row0 + 8;
    if (tg == 0) {
        g_l[sp][n * SEQ + row0] = lacc[0];
        g_l[sp][n * SEQ + row1] = lacc[2];
    }
    float* scr = g_scr[sp];
#pragma unroll
    for (int j = 0; j < 8; j++) {
        const int col = j * 8 + tg * 2;
        *(float2*)(scr + (size_t)(n * SEQ + row0) * DH + col) =
            make_float2(oacc[j][0], oacc[j][1]);
        *(float2*)(scr + (size_t)(n * SEQ + row1) * DH + col) =
            make_float2(oacc[j][2], oacc[j][3]);
    }
}

__global__ __launch_bounds__(256, 8)
void combine_kernel(float* __restrict__ O) {
#pragma unroll
    for (int h = 0; h < 2; h++) {
        const int i = blockIdx.x * 512 + h * 256 + threadIdx.x;
        const int row = i >> 4;
        float4 a = ((const float4*)g_scr[0])[i];
        float l = g_l[0][row];
#pragma unroll
        for (int s = 1; s < KS; s++) {
            const float4 b = ((const float4*)g_scr[s])[i];
            a.x += b.x; a.y += b.y; a.z += b.z; a.w += b.w;
            l += g_l[s][row];
        }
        const float inv = 1.0f / l;
        ((float4*)O)[i] = make_float4(a.x * inv, a.y * inv, a.z * inv, a.w * inv);
    }
}

extern "C" void kernel_launch(void* const* d_in, const int* in_sizes, int n_in,
                              void* d_out, int out_size) {
    const float* Q      = (const float*)d_in[0];
    const float* K      = (const float*)d_in[1];
    const float* V      = (const float*)d_in[2];
    const int*   prefix = (const int*)d_in[3];
    float*       O      = (float*)d_out;

    cudaFuncSetAttribute(attn_part_kernel,
                         cudaFuncAttributeMaxDynamicSharedMemorySize, SM_TOTAL);
    attn_part_kernel<<<dim3(16, 8, KS), 256, SM_TOTAL>>>(Q, K, V, prefix);
    combine_kernel<<<(8 * SEQ * DH / 4) / 512, 256>>>(O);
}

// round 8
// speedup vs baseline: 2.2718x; 1.1158x over previous
#include <cuda_runtime.h>
#include <cuda_fp16.h>
#include <cstdint>

// Block-causal attention, mma.sync fp16 (fp32 accumulate), ex2.approx.f16x2
// softmax producing P directly in fp16 A-fragments, l via ones-column MMA.
// KSPLIT=4 over s-tiles, fp16 partials in scratch + additive combine.
// Interior prefix tiles take a maskless softmax fast path.

#define SEQ 2048
#define DH  64
#define QT  128
#define ST  64
#define PITCHB 144
#define KS  4

#define SM_Q   0
#define SM_K   (SM_Q + 128 * PITCHB)     // 18432
#define SM_V   (SM_K + 64 * PITCHB)      // 27648 (72 rows: 64 data + ones + 7 zero)
#define SM_TOTAL (SM_V + 72 * PITCHB)    // 38016

__device__ __half g_scr[KS][8 * SEQ * DH];   // 8 MB fp16 partials
__device__ float  g_l[KS][8 * SEQ];

__device__ __forceinline__ uint32_t smem_u32(const void* p) {
    uint32_t a;
    asm("{ .reg .u64 t; cvta.to.shared.u64 t, %1; cvt.u32.u64 %0, t; }"
        : "=r"(a) : "l"(p));
    return a;
}
#define LDSM_X4(r, a) \
    asm volatile("ldmatrix.sync.aligned.m8n8.x4.shared.b16 {%0,%1,%2,%3}, [%4];" \
        : "=r"((r)[0]), "=r"((r)[1]), "=r"((r)[2]), "=r"((r)[3]) : "r"(a))
#define LDSM_X2(r, a) \
    asm volatile("ldmatrix.sync.aligned.m8n8.x2.shared.b16 {%0,%1}, [%2];" \
        : "=r"((r)[0]), "=r"((r)[1]) : "r"(a))

__device__ __forceinline__ void mma_f16(float* c, const uint32_t* a, const uint32_t* b) {
    asm volatile(
        "mma.sync.aligned.m16n8k16.row.col.f32.f16.f16.f32 "
        "{%0,%1,%2,%3}, {%4,%5,%6,%7}, {%8,%9}, {%0,%1,%2,%3};"
        : "+f"(c[0]), "+f"(c[1]), "+f"(c[2]), "+f"(c[3])
        : "r"(a[0]), "r"(a[1]), "r"(a[2]), "r"(a[3]), "r"(b[0]), "r"(b[1]));
}
__device__ __forceinline__ uint32_t packh(__half a, __half b) {
    __half2 t; t.x = a; t.y = b;
    return *reinterpret_cast<uint32_t*>(&t);
}
__device__ __forceinline__ uint4 cvt8h(const float* x) {
    uint32_t h[4];
#pragma unroll
    for (int m = 0; m < 4; m++)
        h[m] = packh(__float2half_rn(x[2 * m]), __float2half_rn(x[2 * m + 1]));
    return make_uint4(h[0], h[1], h[2], h[3]);
}
__device__ __forceinline__ uint32_t exp2_pair(float lo, float hi) {
    uint32_t t;
    asm("cvt.rn.f16x2.f32 %0, %1, %2;" : "=r"(t) : "f"(hi), "f"(lo));
    asm("ex2.approx.f16x2 %0, %0;" : "+r"(t));
    return t;
}
__device__ __forceinline__ uint32_t pack2h(float a, float b) {
    uint32_t t;
    asm("cvt.rn.f16x2.f32 %0, %1, %2;" : "=r"(t) : "f"(b), "f"(a));
    return t;
}

__global__ __launch_bounds__(256, 2)
void attn_part_kernel(const float* __restrict__ Q, const float* __restrict__ K,
                      const float* __restrict__ V, const int* __restrict__ prefix) {
    extern __shared__ char smem[];
    const uint32_t sb = smem_u32(smem);
    const int tid  = threadIdx.x;
    const int lane = tid & 31;
    const int w    = tid >> 5;
    const int tg   = lane & 3;
    const int g    = lane >> 2;
    const int n    = blockIdx.y;
    const int qb   = blockIdx.x;
    const int sp   = blockIdx.z;
    const int q0   = qb * QT;
    const int P    = prefix[n];
    const int m0   = w * 16;

    // ---- Q tile -> smem fp16; ones row (64) / zero rows (65-71) of Vt ----
#pragma unroll
    for (int gi = 0; gi < 2; gi++) {
        const int gg = tid + 256 * gi;
        const int r = gg >> 2, d8 = (gg & 3) * 16;
        float x[8];
        const float* qp = Q + (size_t)(n * SEQ + q0 + r) * DH + d8;
        *(float4*)&x[0] = *(const float4*)qp;
        *(float4*)&x[4] = *(const float4*)(qp + 4);
        *(uint4*)(smem + SM_Q + r * PITCHB + d8 * 2) = cvt8h(x);
        float y[8];
        *(float4*)&y[0] = *(const float4*)(qp + 8);
        *(float4*)&y[4] = *(const float4*)(qp + 12);
        *(uint4*)(smem + SM_Q + r * PITCHB + d8 * 2 + 16) = cvt8h(y);
    }
    {
        uint32_t* vz = (uint32_t*)(smem + SM_V + 64 * PITCHB);
        for (int i = tid; i < 8 * PITCHB / 4; i += 256) vz[i] = 0;
        __syncthreads();
        if (tid < 32) vz[tid] = 0x3C003C00u;   // fp16 ones, row 64 cols 0-63
    }
    __syncthreads();

    // ---- Q A-fragments in registers ----
    uint32_t qh[4][4];
    {
        const uint32_t abase = sb + SM_Q + (m0 + (lane & 15)) * PITCHB +
                               ((lane >> 4) & 1) * 16;
#pragma unroll
        for (int kk = 0; kk < 4; kk++) LDSM_X4(qh[kk], abase + kk * 32);
    }

    float oacc[8][4], lacc[4];
#pragma unroll
    for (int j = 0; j < 8; j++)
#pragma unroll
        for (int e = 0; e < 4; e++) oacc[j][e] = 0.0f;
#pragma unroll
    for (int e = 0; e < 4; e++) lacc[e] = 0.0f;

    // ---- tile schedule ----
    const int T = (P + ST - 1) / ST;
    const int dA = qb * 2, dB = qb * 2 + 1;
    const int nPref = (T > sp) ? ((T - sp + 3) >> 2) : 0;
    const bool hasA = (dA >= T) && ((dA & (KS - 1)) == sp);
    const bool hasB = (dB >= T) && ((dB & (KS - 1)) == sp);
    const int nIter = nPref + (hasA ? 1 : 0) + (hasB ? 1 : 0);
    auto tile_of = [&](int it) -> int {
        if (it < nPref) return KS * it + sp;
        if (hasA && it == nPref) return dA;
        return dB;
    };

    const uint32_t boff =
        ((((lane >> 4) & 1) * 8 + (lane & 7)) * PITCHB) + ((lane >> 3) & 1) * 16;
    const uint32_t bK = sb + SM_K + boff;
    const uint32_t bV = sb + SM_V + boff;
    const uint32_t bOnes = sb + SM_V + (64 + (lane & 7)) * PITCHB +
                           ((lane >> 3) & 1) * 16;

    // ---- prefetch tile 0 ----
    float kx[2][8], vx[2][8];
    if (nIter > 0) {
        const int s0n = tile_of(0) * ST;
#pragma unroll
        for (int gi = 0; gi < 2; gi++) {
            const int gg = tid + 256 * gi;
            const int kr = gg >> 3, kd = (gg & 7) * 8;
            const float* kp = K + (size_t)(n * SEQ + s0n + kr) * DH + kd;
            *(float4*)&kx[gi][0] = *(const float4*)kp;
            *(float4*)&kx[gi][4] = *(const float4*)(kp + 4);
            const int vv = gg & 63, vs8 = (gg >> 6) * 8;
#pragma unroll
            for (int k = 0; k < 8; k++)
                vx[gi][k] = V[(size_t)(n * SEQ + s0n + vs8 + k) * DH + vv];
        }
    }

    const float C = 0.18033688011112042f;   // log2(e)/8
    for (int it = 0; it < nIter; ++it) {
        const int s0 = tile_of(it) * ST;

        __syncthreads();
#pragma unroll
        for (int gi = 0; gi < 2; gi++) {
            const int gg = tid + 256 * gi;
            const int kr = gg >> 3, kd = (gg & 7) * 8;
            *(uint4*)(smem + SM_K + kr * PITCHB + kd * 2) = cvt8h(kx[gi]);
            const int vv = gg & 63, vs8 = (gg >> 6) * 8;
            *(uint4*)(smem + SM_V + vv * PITCHB + vs8 * 2) = cvt8h(vx[gi]);
        }
        __syncthreads();

        if (it + 1 < nIter) {
            const int s0n = tile_of(it + 1) * ST;
#pragma unroll
            for (int gi = 0; gi < 2; gi++) {
                const int gg = tid + 256 * gi;
                const int kr = gg >> 3, kd = (gg & 7) * 8;
                const float* kp = K + (size_t)(n * SEQ + s0n + kr) * DH + kd;
                *(float4*)&kx[gi][0] = *(const float4*)kp;
                *(float4*)&kx[gi][4] = *(const float4*)(kp + 4);
                const int vv = gg & 63, vs8 = (gg >> 6) * 8;
#pragma unroll
                for (int k = 0; k < 8; k++)
                    vx[gi][k] = V[(size_t)(n * SEQ + s0n + vs8 + k) * DH + vv];
            }
        }

        // ---- GEMM1: sc = Q @ K^T ----
        float sc[8][4];
#pragma unroll
        for (int j = 0; j < 8; j++)
#pragma unroll
            for (int e = 0; e < 4; e++) sc[j][e] = 0.0f;
#pragma unroll
        for (int jp = 0; jp < 4; jp++) {
            const uint32_t ka = bK + jp * (16 * PITCHB);
#pragma unroll
            for (int kk = 0; kk < 4; kk++) {
                uint32_t bh[4];
                LDSM_X4(bh, ka + kk * 32);
                mma_f16(sc[2 * jp],     qh[kk], bh);
                mma_f16(sc[2 * jp + 1], qh[kk], bh + 2);
            }
        }

        // ---- softmax: maskless fast path for interior tiles ----
        uint32_t pa[8][2];
        if (s0 + ST <= P) {
#pragma unroll
            for (int j = 0; j < 8; j++) {
                pa[j][0] = exp2_pair(sc[j][0] * C, sc[j][1] * C);
                pa[j][1] = exp2_pair(sc[j][2] * C, sc[j][3] * C);
            }
        } else {
            const int row0 = q0 + m0 + g;
            const int row1 = row0 + 8;
#pragma unroll
            for (int j = 0; j < 8; j++) {
                const int cb = s0 + j * 8 + tg * 2;
                const bool ok0 = (cb < P),     okd0 = ok0 || (cb == row0),
                           okd0b = ok0 || (cb == row1);
                const bool ok1 = (cb + 1 < P), okd1 = ok1 || (cb + 1 == row0),
                           okd1b = ok1 || (cb + 1 == row1);
                const float a0 = okd0  ? sc[j][0] * C : -1e30f;
                const float a1 = okd1  ? sc[j][1] * C : -1e30f;
                const float a2 = okd0b ? sc[j][2] * C : -1e30f;
                const float a3 = okd1b ? sc[j][3] * C : -1e30f;
                pa[j][0] = exp2_pair(a0, a1);
                pa[j][1] = exp2_pair(a2, a3);
            }
        }

        // ---- GEMM2: O += P @ V; l += P @ ones ----
#pragma unroll
        for (int kb = 0; kb < 4; kb++) {
            uint32_t af[4] = { pa[2 * kb][0], pa[2 * kb][1],
                               pa[2 * kb + 1][0], pa[2 * kb + 1][1] };
            uint32_t bo[2];
            LDSM_X2(bo, bOnes + kb * 32);
            mma_f16(lacc, af, bo);
#pragma unroll
            for (int jp = 0; jp < 4; jp++) {
                const uint32_t va = bV + jp * (16 * PITCHB) + kb * 32;
                uint32_t vh[4];
                LDSM_X4(vh, va);
                mma_f16(oacc[2 * jp],     af, vh);
                mma_f16(oacc[2 * jp + 1], af, vh + 2);
            }
        }
    }

    // ---- write fp16 partials + fp32 l ----
    const int row0 = q0 + m0 + g;
    const int row1 = row0 + 8;
    if (tg == 0) {
        g_l[sp][n * SEQ + row0] = lacc[0];
        g_l[sp][n * SEQ + row1] = lacc[2];
    }
    __half* scr = g_scr[sp];
#pragma unroll
    for (int j = 0; j < 8; j++) {
        const int col = j * 8 + tg * 2;
        *(uint32_t*)(scr + (size_t)(n * SEQ + row0) * DH + col) =
            pack2h(oacc[j][0], oacc[j][1]);
        *(uint32_t*)(scr + (size_t)(n * SEQ + row1) * DH + col) =
            pack2h(oacc[j][2], oacc[j][3]);
    }
}

__global__ __launch_bounds__(256, 8)
void combine_kernel(float* __restrict__ O) {
#pragma unroll
    for (int h = 0; h < 2; h++) {
        const int i = blockIdx.x * 512 + h * 256 + threadIdx.x;  // 4-float group
        const int row = i >> 4;
        float l = 0.0f;
        float4 a = make_float4(0.f, 0.f, 0.f, 0.f);
#pragma unroll
        for (int s = 0; s < KS; s++) {
            const uint2 u = ((const uint2*)g_scr[s])[i];
            const __half2 p0 = *reinterpret_cast<const __half2*>(&u.x);
            const __half2 p1 = *reinterpret_cast<const __half2*>(&u.y);
            a.x += __low2float(p0);  a.y += __high2float(p0);
            a.z += __low2float(p1);  a.w += __high2float(p1);
            l += g_l[s][row];
        }
        const float inv = 1.0f / l;
        ((float4*)O)[i] = make_float4(a.x * inv, a.y * inv, a.z * inv, a.w * inv);
    }
}

extern "C" void kernel_launch(void* const* d_in, const int* in_sizes, int n_in,
                              void* d_out, int out_size) {
    const float* Q      = (const float*)d_in[0];
    const float* K      = (const float*)d_in[1];
    const float* V      = (const float*)d_in[2];
    const int*   prefix = (const int*)d_in[3];
    float*       O      = (float*)d_out;

    cudaFuncSetAttribute(attn_part_kernel,
                         cudaFuncAttributeMaxDynamicSharedMemorySize, SM_TOTAL);
    attn_part_kernel<<<dim3(16, 8, KS), 256, SM_TOTAL>>>(Q, K, V, prefix);
    combine_kernel<<<(8 * SEQ * DH / 4) / 512, 256>>>(O);
}

// round 9
// speedup vs baseline: 2.3690x; 1.0428x over previous
#include <cuda_runtime.h>
#include <cuda_fp16.h>
#include <cstdint>

// Block-causal attention, mma.sync fp16 (fp32 accumulate).
// Round-9: pre-pass converts K->fp16 and V->fp16 (transposed) once; main
// kernel streams tiles via cp.async into double-buffered smem (1 sync/tile).
// ex2.approx.f16x2 softmax -> P directly in fp16 A-fragments; l via
// ones-column MMA. KSPLIT=4 + fp16 partials + additive combine.

#define SEQ 2048
#define DH  64
#define QT  128
#define ST  64
#define PITCHB 144
#define KS  4

#define SM_Q    0
#define SM_KV0  (SM_Q + 128 * PITCHB)        // 18432
#define SM_KV1  (SM_KV0 + 128 * PITCHB)      // 36864
#define SM_ONES (SM_KV1 + 128 * PITCHB)      // 55296
#define SM_TOTAL (SM_ONES + 8 * PITCHB)      // 56448
#define KVBUF   (128 * PITCHB)
#define VOFF    (64 * PITCHB)

__device__ __half g_kh[8 * SEQ * DH];        // fp16 K        [n][s][d]
__device__ __half g_vt[8 * DH * SEQ];        // fp16 V^T      [n][v][s]
__device__ __half g_scr[KS][8 * SEQ * DH];   // fp16 partials
__device__ float  g_l[KS][8 * SEQ];

__device__ __forceinline__ uint32_t smem_u32(const void* p) {
    uint32_t a;
    asm("{ .reg .u64 t; cvta.to.shared.u64 t, %1; cvt.u32.u64 %0, t; }"
        : "=r"(a) : "l"(p));
    return a;
}
__device__ __forceinline__ void cp16(uint32_t smem, const __half* g) {
    asm volatile("cp.async.cg.shared.global [%0], [%1], 16;"
                 :: "r"(smem), "l"(__cvta_generic_to_global(g)) : "memory");
}
#define CP_COMMIT() asm volatile("cp.async.commit_group;" ::: "memory")
#define CP_WAIT0()  asm volatile("cp.async.wait_group 0;" ::: "memory")

#define LDSM_X4(r, a) \
    asm volatile("ldmatrix.sync.aligned.m8n8.x4.shared.b16 {%0,%1,%2,%3}, [%4];" \
        : "=r"((r)[0]), "=r"((r)[1]), "=r"((r)[2]), "=r"((r)[3]) : "r"(a))
#define LDSM_X2(r, a) \
    asm volatile("ldmatrix.sync.aligned.m8n8.x2.shared.b16 {%0,%1}, [%2];" \
        : "=r"((r)[0]), "=r"((r)[1]) : "r"(a))

__device__ __forceinline__ void mma_f16(float* c, const uint32_t* a, const uint32_t* b) {
    asm volatile(
        "mma.sync.aligned.m16n8k16.row.col.f32.f16.f16.f32 "
        "{%0,%1,%2,%3}, {%4,%5,%6,%7}, {%8,%9}, {%0,%1,%2,%3};"
        : "+f"(c[0]), "+f"(c[1]), "+f"(c[2]), "+f"(c[3])
        : "r"(a[0]), "r"(a[1]), "r"(a[2]), "r"(a[3]), "r"(b[0]), "r"(b[1]));
}
__device__ __forceinline__ uint32_t packh(__half a, __half b) {
    __half2 t; t.x = a; t.y = b;
    return *reinterpret_cast<uint32_t*>(&t);
}
__device__ __forceinline__ uint4 cvt8h(const float* x) {
    uint32_t h[4];
#pragma unroll
    for (int m = 0; m < 4; m++)
        h[m] = packh(__float2half_rn(x[2 * m]), __float2half_rn(x[2 * m + 1]));
    return make_uint4(h[0], h[1], h[2], h[3]);
}
__device__ __forceinline__ uint32_t exp2_pair(float lo, float hi) {
    uint32_t t;
    asm("cvt.rn.f16x2.f32 %0, %1, %2;" : "=r"(t) : "f"(hi), "f"(lo));
    asm("ex2.approx.f16x2 %0, %0;" : "+r"(t));
    return t;
}
__device__ __forceinline__ uint32_t pack2h(float a, float b) {
    uint32_t t;
    asm("cvt.rn.f16x2.f32 %0, %1, %2;" : "=r"(t) : "f"(b), "f"(a));
    return t;
}

// ---- pre-pass: K -> fp16 [n][s][d]; V -> fp16 transposed [n][v][s] ----
__global__ __launch_bounds__(256)
void prep_kernel(const float* __restrict__ K, const float* __restrict__ V) {
    const int t = blockIdx.x, n = blockIdx.y;
    const int s0 = t * ST, tid = threadIdx.x;
#pragma unroll
    for (int gi = 0; gi < 2; gi++) {
        const int gg = tid + 256 * gi;
        const int kr = gg >> 3, kd = (gg & 7) * 8;
        float x[8];
        const float* kp = K + (size_t)(n * SEQ + s0 + kr) * DH + kd;
        *(float4*)&x[0] = *(const float4*)kp;
        *(float4*)&x[4] = *(const float4*)(kp + 4);
        *(uint4*)&g_kh[(size_t)(n * SEQ + s0 + kr) * DH + kd] = cvt8h(x);

        const int vv = gg & 63, vs8 = (gg >> 6) * 8;
        float vx[8];
#pragma unroll
        for (int k = 0; k < 8; k++)
            vx[k] = V[(size_t)(n * SEQ + s0 + vs8 + k) * DH + vv];
        *(uint4*)&g_vt[(size_t)(n * DH + vv) * SEQ + s0 + vs8] = cvt8h(vx);
    }
}

__global__ __launch_bounds__(256, 2)
void attn_part_kernel(const float* __restrict__ Q, const int* __restrict__ prefix) {
    extern __shared__ char smem[];
    const uint32_t sb = smem_u32(smem);
    const int tid  = threadIdx.x;
    const int lane = tid & 31;
    const int w    = tid >> 5;
    const int tg   = lane & 3;
    const int g    = lane >> 2;
    const int n    = blockIdx.y;
    const int qb   = blockIdx.x;
    const int sp   = blockIdx.z;
    const int q0   = qb * QT;
    const int P    = prefix[n];
    const int m0   = w * 16;

    // ---- Q tile -> smem fp16; ones region ----
#pragma unroll
    for (int gi = 0; gi < 2; gi++) {
        const int gg = tid + 256 * gi;
        const int r = gg >> 2, d8 = (gg & 3) * 16;
        float x[8];
        const float* qp = Q + (size_t)(n * SEQ + q0 + r) * DH + d8;
        *(float4*)&x[0] = *(const float4*)qp;
        *(float4*)&x[4] = *(const float4*)(qp + 4);
        *(uint4*)(smem + SM_Q + r * PITCHB + d8 * 2) = cvt8h(x);
        float y[8];
        *(float4*)&y[0] = *(const float4*)(qp + 8);
        *(float4*)&y[4] = *(const float4*)(qp + 12);
        *(uint4*)(smem + SM_Q + r * PITCHB + d8 * 2 + 16) = cvt8h(y);
    }
    {
        uint32_t* vz = (uint32_t*)(smem + SM_ONES);
        for (int i = tid; i < 8 * PITCHB / 4; i += 256) vz[i] = 0;
    }
    __syncthreads();
    if (tid < 32)
        ((uint32_t*)(smem + SM_ONES))[tid] = 0x3C003C00u;  // row 0: fp16 ones x64
    __syncthreads();

    // ---- Q A-fragments ----
    uint32_t qh[4][4];
    {
        const uint32_t abase = sb + SM_Q + (m0 + (lane & 15)) * PITCHB +
                               ((lane >> 4) & 1) * 16;
#pragma unroll
        for (int kk = 0; kk < 4; kk++) LDSM_X4(qh[kk], abase + kk * 32);
    }

    float oacc[8][4], lacc[4];
#pragma unroll
    for (int j = 0; j < 8; j++)
#pragma unroll
        for (int e = 0; e < 4; e++) oacc[j][e] = 0.0f;
#pragma unroll
    for (int e = 0; e < 4; e++) lacc[e] = 0.0f;

    // ---- tile schedule ----
    const int T = (P + ST - 1) / ST;
    const int dA = qb * 2, dB = qb * 2 + 1;
    const int nPref = (T > sp) ? ((T - sp + 3) >> 2) : 0;
    const bool hasA = (dA >= T) && ((dA & (KS - 1)) == sp);
    const bool hasB = (dB >= T) && ((dB & (KS - 1)) == sp);
    const int nIter = nPref + (hasA ? 1 : 0) + (hasB ? 1 : 0);
    auto tile_of = [&](int it) -> int {
        if (it < nPref) return KS * it + sp;
        if (hasA && it == nPref) return dA;
        return dB;
    };

    // per-thread cp.async slots
    const int kr = tid >> 3, kd8 = (tid & 7) * 8;       // K row / 16B slot (first half)
    const int kr2 = kr + 32;                            // second half rows
    const int vv = tid & 63, vs8 = (tid >> 6) * 8;      // Vt row / s-slot
    const int vs8b = vs8 + 32;

    auto issue_tile = [&](int t, int buf) {
        const int s0t = t * ST;
        const uint32_t kb = sb + SM_KV0 + buf * KVBUF;
        const uint32_t vb = kb + VOFF;
        cp16(kb + kr  * PITCHB + kd8 * 2, &g_kh[(size_t)(n * SEQ + s0t + kr)  * DH + kd8]);
        cp16(kb + kr2 * PITCHB + kd8 * 2, &g_kh[(size_t)(n * SEQ + s0t + kr2) * DH + kd8]);
        cp16(vb + vv * PITCHB + vs8  * 2, &g_vt[(size_t)(n * DH + vv) * SEQ + s0t + vs8]);
        cp16(vb + vv * PITCHB + vs8b * 2, &g_vt[(size_t)(n * DH + vv) * SEQ + s0t + vs8b]);
        CP_COMMIT();
    };

    const uint32_t boff =
        ((((lane >> 4) & 1) * 8 + (lane & 7)) * PITCHB) + ((lane >> 3) & 1) * 16;
    const uint32_t bOnes = sb + SM_ONES + (lane & 7) * PITCHB + ((lane >> 3) & 1) * 16;

    if (nIter > 0) issue_tile(tile_of(0), 0);

    const float C = 0.18033688011112042f;   // log2(e)/8
    for (int it = 0; it < nIter; ++it) {
        const int s0 = tile_of(it) * ST;
        const int buf = it & 1;

        CP_WAIT0();
        __syncthreads();   // tile `it` landed for all threads; prev compute done

        if (it + 1 < nIter) issue_tile(tile_of(it + 1), buf ^ 1);

        const uint32_t bK = sb + SM_KV0 + buf * KVBUF + boff;
        const uint32_t bV = bK + VOFF;

        // ---- GEMM1: sc = Q @ K^T ----
        float sc[8][4];
#pragma unroll
        for (int j = 0; j < 8; j++)
#pragma unroll
            for (int e = 0; e < 4; e++) sc[j][e] = 0.0f;
#pragma unroll
        for (int jp = 0; jp < 4; jp++) {
            const uint32_t ka = bK + jp * (16 * PITCHB);
#pragma unroll
            for (int kk = 0; kk < 4; kk++) {
                uint32_t bh[4];
                LDSM_X4(bh, ka + kk * 32);
                mma_f16(sc[2 * jp],     qh[kk], bh);
                mma_f16(sc[2 * jp + 1], qh[kk], bh + 2);
            }
        }

        // ---- softmax (maskless fast path for interior tiles) ----
        uint32_t pa[8][2];
        if (s0 + ST <= P) {
#pragma unroll
            for (int j = 0; j < 8; j++) {
                pa[j][0] = exp2_pair(sc[j][0] * C, sc[j][1] * C);
                pa[j][1] = exp2_pair(sc[j][2] * C, sc[j][3] * C);
            }
        } else {
            const int row0 = q0 + m0 + g;
            const int row1 = row0 + 8;
#pragma unroll
            for (int j = 0; j < 8; j++) {
                const int cb = s0 + j * 8 + tg * 2;
                const bool ok0 = (cb < P),     okd0 = ok0 || (cb == row0),
                           okd0b = ok0 || (cb == row1);
                const bool ok1 = (cb + 1 < P), okd1 = ok1 || (cb + 1 == row0),
                           okd1b = ok1 || (cb + 1 == row1);
                const float a0 = okd0  ? sc[j][0] * C : -1e30f;
                const float a1 = okd1  ? sc[j][1] * C : -1e30f;
                const float a2 = okd0b ? sc[j][2] * C : -1e30f;
                const float a3 = okd1b ? sc[j][3] * C : -1e30f;
                pa[j][0] = exp2_pair(a0, a1);
                pa[j][1] = exp2_pair(a2, a3);
            }
        }

        // ---- GEMM2: O += P @ V; l += P @ ones ----
#pragma unroll
        for (int kb = 0; kb < 4; kb++) {
            uint32_t af[4] = { pa[2 * kb][0], pa[2 * kb][1],
                               pa[2 * kb + 1][0], pa[2 * kb + 1][1] };
            uint32_t bo[2];
            LDSM_X2(bo, bOnes + kb * 32);
            mma_f16(lacc, af, bo);
#pragma unroll
            for (int jp = 0; jp < 4; jp++) {
                const uint32_t va = bV + jp * (16 * PITCHB) + kb * 32;
                uint32_t vh[4];
                LDSM_X4(vh, va);
                mma_f16(oacc[2 * jp],     af, vh);
                mma_f16(oacc[2 * jp + 1], af, vh + 2);
            }
        }
        __syncthreads();   // all warps done reading buf before it's refilled at it+2
    }

    // ---- write fp16 partials + fp32 l ----
    const int row0 = q0 + m0 + g;
    const int row1 = row0 + 8;
    if (tg == 0) {
        g_l[sp][n * SEQ + row0] = lacc[0];
        g_l[sp][n * SEQ + row1] = lacc[2];
    }
    __half* scr = g_scr[sp];
#pragma unroll
    for (int j = 0; j < 8; j++) {
        const int col = j * 8 + tg * 2;
        *(uint32_t*)(scr + (size_t)(n * SEQ + row0) * DH + col) =
            pack2h(oacc[j][0], oacc[j][1]);
        *(uint32_t*)(scr + (size_t)(n * SEQ + row1) * DH + col) =
            pack2h(oacc[j][2], oacc[j][3]);
    }
}

__global__ __launch_bounds__(256, 8)
void combine_kernel(float* __restrict__ O) {
#pragma unroll
    for (int h = 0; h < 2; h++) {
        const int i = blockIdx.x * 512 + h * 256 + threadIdx.x;
        const int row = i >> 4;
        float l = 0.0f;
        float4 a = make_float4(0.f, 0.f, 0.f, 0.f);
#pragma unroll
        for (int s = 0; s < KS; s++) {
            const uint2 u = ((const uint2*)g_scr[s])[i];
            const __half2 p0 = *reinterpret_cast<const __half2*>(&u.x);
            const __half2 p1 = *reinterpret_cast<const __half2*>(&u.y);
            a.x += __low2float(p0);  a.y += __high2float(p0);
            a.z += __low2float(p1);  a.w += __high2float(p1);
            l += g_l[s][row];
        }
        const float inv = 1.0f / l;
        ((float4*)O)[i] = make_float4(a.x * inv, a.y * inv, a.z * inv, a.w * inv);
    }
}

extern "C" void kernel_launch(void* const* d_in, const int* in_sizes, int n_in,
                              void* d_out, int out_size) {
    const float* Q      = (const float*)d_in[0];
    const float* K      = (const float*)d_in[1];
    const float* V      = (const float*)d_in[2];
    const int*   prefix = (const int*)d_in[3];
    float*       O      = (float*)d_out;

    prep_kernel<<<dim3(32, 8), 256>>>(K, V);
    cudaFuncSetAttribute(attn_part_kernel,
                         cudaFuncAttributeMaxDynamicSharedMemorySize, SM_TOTAL);
    attn_part_kernel<<<dim3(16, 8, KS), 256, SM_TOTAL>>>(Q, prefix);
    combine_kernel<<<(8 * SEQ * DH / 4) / 512, 256>>>(O);
}

// round 10
// speedup vs baseline: 2.4530x; 1.0355x over previous
#include <cuda_runtime.h>
#include <cuda_fp16.h>
#include <cstdint>

// Block-causal attention, mma.sync fp16 (fp32 accumulate).
// Round-10: prep does smem-staged coalesced V transpose; main kernel streams
// fp16 K/Vt tiles via cp.async double-buffer (1 sync/tile), constant ones
// B-fragment for the l-MMA (no smem ones region). KSPLIT=4, fp16 partials,
// additive combine at higher concurrency.

#define SEQ 2048
#define DH  64
#define QT  128
#define ST  64
#define PITCHB 144
#define KS  4

#define SM_Q    0
#define SM_KV0  (SM_Q + 128 * PITCHB)        // 18432
#define SM_KV1  (SM_KV0 + 128 * PITCHB)      // 36864
#define SM_TOTAL (SM_KV1 + 128 * PITCHB)     // 55296
#define KVBUF   (128 * PITCHB)
#define VOFF    (64 * PITCHB)

__device__ __half g_kh[8 * SEQ * DH];        // fp16 K   [n][s][d]
__device__ __half g_vt[8 * DH * SEQ];        // fp16 V^T [n][v][s]
__device__ __half g_scr[KS][8 * SEQ * DH];   // fp16 partials
__device__ float  g_l[KS][8 * SEQ];

__device__ __forceinline__ uint32_t smem_u32(const void* p) {
    uint32_t a;
    asm("{ .reg .u64 t; cvta.to.shared.u64 t, %1; cvt.u32.u64 %0, t; }"
        : "=r"(a) : "l"(p));
    return a;
}
__device__ __forceinline__ void cp16(uint32_t smem, const __half* g) {
    asm volatile("cp.async.cg.shared.global [%0], [%1], 16;"
                 :: "r"(smem), "l"(__cvta_generic_to_global(g)) : "memory");
}
#define CP_COMMIT() asm volatile("cp.async.commit_group;" ::: "memory")
#define CP_WAIT0()  asm volatile("cp.async.wait_group 0;" ::: "memory")

#define LDSM_X4(r, a) \
    asm volatile("ldmatrix.sync.aligned.m8n8.x4.shared.b16 {%0,%1,%2,%3}, [%4];" \
        : "=r"((r)[0]), "=r"((r)[1]), "=r"((r)[2]), "=r"((r)[3]) : "r"(a))

__device__ __forceinline__ void mma_f16(float* c, const uint32_t* a, const uint32_t* b) {
    asm volatile(
        "mma.sync.aligned.m16n8k16.row.col.f32.f16.f16.f32 "
        "{%0,%1,%2,%3}, {%4,%5,%6,%7}, {%8,%9}, {%0,%1,%2,%3};"
        : "+f"(c[0]), "+f"(c[1]), "+f"(c[2]), "+f"(c[3])
        : "r"(a[0]), "r"(a[1]), "r"(a[2]), "r"(a[3]), "r"(b[0]), "r"(b[1]));
}
__device__ __forceinline__ uint32_t packh(__half a, __half b) {
    __half2 t; t.x = a; t.y = b;
    return *reinterpret_cast<uint32_t*>(&t);
}
__device__ __forceinline__ uint4 cvt8h(const float* x) {
    uint32_t h[4];
#pragma unroll
    for (int m = 0; m < 4; m++)
        h[m] = packh(__float2half_rn(x[2 * m]), __float2half_rn(x[2 * m + 1]));
    return make_uint4(h[0], h[1], h[2], h[3]);
}
__device__ __forceinline__ uint32_t exp2_pair(float lo, float hi) {
    uint32_t t;
    asm("cvt.rn.f16x2.f32 %0, %1, %2;" : "=r"(t) : "f"(hi), "f"(lo));
    asm("ex2.approx.f16x2 %0, %0;" : "+r"(t));
    return t;
}
__device__ __forceinline__ uint32_t pack2h(float a, float b) {
    uint32_t t;
    asm("cvt.rn.f16x2.f32 %0, %1, %2;" : "=r"(t) : "f"(b), "f"(a));
    return t;
}

// ---- pre-pass: K -> fp16 [n][s][d]; V -> fp16 transposed [n][v][s] ----
// V transpose staged through swizzled smem: coalesced float4 in, coalesced
// 16B out. Swizzle: byte_in_row ^= 16 * ((row >> 3) & 7).
__global__ __launch_bounds__(256)
void prep_kernel(const float* __restrict__ K, const float* __restrict__ V) {
    __shared__ __align__(16) char vs[64 * PITCHB];
    const int t = blockIdx.x, n = blockIdx.y;
    const int s0 = t * ST, tid = threadIdx.x;

#pragma unroll
    for (int gi = 0; gi < 2; gi++) {
        const int gg = tid + 256 * gi;
        const int r = gg >> 3, d8 = (gg & 7) * 8;
        // K: convert in place layout
        float x[8];
        const float* kp = K + (size_t)(n * SEQ + s0 + r) * DH + d8;
        *(float4*)&x[0] = *(const float4*)kp;
        *(float4*)&x[4] = *(const float4*)(kp + 4);
        *(uint4*)&g_kh[(size_t)(n * SEQ + s0 + r) * DH + d8] = cvt8h(x);
        // V: row-major load -> swizzled smem
        float y[8];
        const float* vp = V + (size_t)(n * SEQ + s0 + r) * DH + d8;
        *(float4*)&y[0] = *(const float4*)vp;
        *(float4*)&y[4] = *(const float4*)(vp + 4);
        const uint32_t off = r * PITCHB + ((d8 * 2) ^ (((r >> 3) & 7) * 16));
        *(uint4*)(vs + off) = cvt8h(y);
    }
    __syncthreads();

    // transposed write-out: thread (v, s8) packs 8 halves along s
#pragma unroll
    for (int gi = 0; gi < 2; gi++) {
        const int oi = tid + 256 * gi;          // 0..511
        const int v = oi >> 3, s8 = (oi & 7) * 8;
        uint32_t wv[4];
#pragma unroll
        for (int k2 = 0; k2 < 4; k2++) {
            const int r0 = s8 + 2 * k2, r1 = r0 + 1;
            const uint16_t h0 = *(const uint16_t*)
                (vs + r0 * PITCHB + ((2 * v) ^ (((r0 >> 3) & 7) * 16)));
            const uint16_t h1 = *(const uint16_t*)
                (vs + r1 * PITCHB + ((2 * v) ^ (((r1 >> 3) & 7) * 16)));
            wv[k2] = (uint32_t)h0 | ((uint32_t)h1 << 16);
        }
        *(uint4*)&g_vt[(size_t)(n * DH + v) * SEQ + s0 + s8] =
            make_uint4(wv[0], wv[1], wv[2], wv[3]);
    }
}

__global__ __launch_bounds__(256, 2)
void attn_part_kernel(const float* __restrict__ Q, const int* __restrict__ prefix) {
    extern __shared__ char smem[];
    const uint32_t sb = smem_u32(smem);
    const int tid  = threadIdx.x;
    const int lane = tid & 31;
    const int w    = tid >> 5;
    const int tg   = lane & 3;
    const int g    = lane >> 2;
    const int n    = blockIdx.y;
    const int qb   = blockIdx.x;
    const int sp   = blockIdx.z;
    const int q0   = qb * QT;
    const int P    = prefix[n];
    const int m0   = w * 16;

    // ---- Q tile -> smem fp16 ----
#pragma unroll
    for (int gi = 0; gi < 2; gi++) {
        const int gg = tid + 256 * gi;
        const int r = gg >> 2, d8 = (gg & 3) * 16;
        float x[8];
        const float* qp = Q + (size_t)(n * SEQ + q0 + r) * DH + d8;
        *(float4*)&x[0] = *(const float4*)qp;
        *(float4*)&x[4] = *(const float4*)(qp + 4);
        *(uint4*)(smem + SM_Q + r * PITCHB + d8 * 2) = cvt8h(x);
        float y[8];
        *(float4*)&y[0] = *(const float4*)(qp + 8);
        *(float4*)&y[4] = *(const float4*)(qp + 12);
        *(uint4*)(smem + SM_Q + r * PITCHB + d8 * 2 + 16) = cvt8h(y);
    }
    __syncthreads();

    // ---- Q A-fragments ----
    uint32_t qh[4][4];
    {
        const uint32_t abase = sb + SM_Q + (m0 + (lane & 15)) * PITCHB +
                               ((lane >> 4) & 1) * 16;
#pragma unroll
        for (int kk = 0; kk < 4; kk++) LDSM_X4(qh[kk], abase + kk * 32);
    }

    float oacc[8][4], lacc[4];
#pragma unroll
    for (int j = 0; j < 8; j++)
#pragma unroll
        for (int e = 0; e < 4; e++) oacc[j][e] = 0.0f;
#pragma unroll
    for (int e = 0; e < 4; e++) lacc[e] = 0.0f;

    // ---- tile schedule ----
    const int T = (P + ST - 1) / ST;
    const int dA = qb * 2, dB = qb * 2 + 1;
    const int nPref = (T > sp) ? ((T - sp + 3) >> 2) : 0;
    const bool hasA = (dA >= T) && ((dA & (KS - 1)) == sp);
    const bool hasB = (dB >= T) && ((dB & (KS - 1)) == sp);
    const int nIter = nPref + (hasA ? 1 : 0) + (hasB ? 1 : 0);
    auto tile_of = [&](int it) -> int {
        if (it < nPref) return KS * it + sp;
        if (hasA && it == nPref) return dA;
        return dB;
    };

    // per-thread cp.async slots
    const int kr = tid >> 3, kd8 = (tid & 7) * 8;
    const int kr2 = kr + 32;
    const int vv = tid & 63, vs8 = (tid >> 6) * 8;
    const int vs8b = vs8 + 32;

    auto issue_tile = [&](int t, int buf) {
        const int s0t = t * ST;
        const uint32_t kb = sb + SM_KV0 + buf * KVBUF;
        const uint32_t vb = kb + VOFF;
        cp16(kb + kr  * PITCHB + kd8 * 2, &g_kh[(size_t)(n * SEQ + s0t + kr)  * DH + kd8]);
        cp16(kb + kr2 * PITCHB + kd8 * 2, &g_kh[(size_t)(n * SEQ + s0t + kr2) * DH + kd8]);
        cp16(vb + vv * PITCHB + vs8  * 2, &g_vt[(size_t)(n * DH + vv) * SEQ + s0t + vs8]);
        cp16(vb + vv * PITCHB + vs8b * 2, &g_vt[(size_t)(n * DH + vv) * SEQ + s0t + vs8b]);
        CP_COMMIT();
    };

    const uint32_t boff =
        ((((lane >> 4) & 1) * 8 + (lane & 7)) * PITCHB) + ((lane >> 3) & 1) * 16;

    // constant ones B-fragment for the l-MMA (B[k][0]=1, cols 1..7 = 0):
    // fragment element (k, n=lane/4) -> nonzero only for lane/4 == 0.
    const uint32_t bone = (g == 0) ? 0x3C003C00u : 0u;
    const uint32_t bo[2] = { bone, bone };

    if (nIter > 0) issue_tile(tile_of(0), 0);

    const float C = 0.18033688011112042f;   // log2(e)/8
    for (int it = 0; it < nIter; ++it) {
        const int s0 = tile_of(it) * ST;
        const int buf = it & 1;

        CP_WAIT0();
        __syncthreads();  // tile `it` landed; all warps done with buf^1 compute

        if (it + 1 < nIter) issue_tile(tile_of(it + 1), buf ^ 1);

        const uint32_t bK = sb + SM_KV0 + buf * KVBUF + boff;
        const uint32_t bV = bK + VOFF;

        // ---- GEMM1: sc = Q @ K^T ----
        float sc[8][4];
#pragma unroll
        for (int j = 0; j < 8; j++)
#pragma unroll
            for (int e = 0; e < 4; e++) sc[j][e] = 0.0f;
#pragma unroll
        for (int jp = 0; jp < 4; jp++) {
            const uint32_t ka = bK + jp * (16 * PITCHB);
#pragma unroll
            for (int kk = 0; kk < 4; kk++) {
                uint32_t bh[4];
                LDSM_X4(bh, ka + kk * 32);
                mma_f16(sc[2 * jp],     qh[kk], bh);
                mma_f16(sc[2 * jp + 1], qh[kk], bh + 2);
            }
        }

        // ---- softmax (maskless fast path for interior tiles) ----
        uint32_t pa[8][2];
        if (s0 + ST <= P) {
#pragma unroll
            for (int j = 0; j < 8; j++) {
                pa[j][0] = exp2_pair(sc[j][0] * C, sc[j][1] * C);
                pa[j][1] = exp2_pair(sc[j][2] * C, sc[j][3] * C);
            }
        } else {
            const int row0 = q0 + m0 + g;
            const int row1 = row0 + 8;
#pragma unroll
            for (int j = 0; j < 8; j++) {
                const int cb = s0 + j * 8 + tg * 2;
                const bool ok0 = (cb < P),     okd0 = ok0 || (cb == row0),
                           okd0b = ok0 || (cb == row1);
                const bool ok1 = (cb + 1 < P), okd1 = ok1 || (cb + 1 == row0),
                           okd1b = ok1 || (cb + 1 == row1);
                const float a0 = okd0  ? sc[j][0] * C : -1e30f;
                const float a1 = okd1  ? sc[j][1] * C : -1e30f;
                const float a2 = okd0b ? sc[j][2] * C : -1e30f;
                const float a3 = okd1b ? sc[j][3] * C : -1e30f;
                pa[j][0] = exp2_pair(a0, a1);
                pa[j][1] = exp2_pair(a2, a3);
            }
        }

        // ---- GEMM2: O += P @ V; l += P @ ones (constant fragment) ----
#pragma unroll
        for (int kb = 0; kb < 4; kb++) {
            uint32_t af[4] = { pa[2 * kb][0], pa[2 * kb][1],
                               pa[2 * kb + 1][0], pa[2 * kb + 1][1] };
            mma_f16(lacc, af, bo);
#pragma unroll
            for (int jp = 0; jp < 4; jp++) {
                const uint32_t va = bV + jp * (16 * PITCHB) + kb * 32;
                uint32_t vh[4];
                LDSM_X4(vh, va);
                mma_f16(oacc[2 * jp],     af, vh);
                mma_f16(oacc[2 * jp + 1], af, vh + 2);
            }
        }
    }

    // ---- write fp16 partials + fp32 l ----
    const int row0 = q0 + m0 + g;
    const int row1 = row0 + 8;
    if (tg == 0) {
        g_l[sp][n * SEQ + row0] = lacc[0];
        g_l[sp][n * SEQ + row1] = lacc[2];
    }
    __half* scr = g_scr[sp];
#pragma unroll
    for (int j = 0; j < 8; j++) {
        const int col = j * 8 + tg * 2;
        *(uint32_t*)(scr + (size_t)(n * SEQ + row0) * DH + col) =
            pack2h(oacc[j][0], oacc[j][1]);
        *(uint32_t*)(scr + (size_t)(n * SEQ + row1) * DH + col) =
            pack2h(oacc[j][2], oacc[j][3]);
    }
}

__global__ __launch_bounds__(256, 8)
void combine_kernel(float* __restrict__ O) {
    const int i = blockIdx.x * 256 + threadIdx.x;   // float4 index, 262144 total
    const int row = i >> 4;
    float l = 0.0f;
    float4 a = make_float4(0.f, 0.f, 0.f, 0.f);
#pragma unroll
    for (int s = 0; s < KS; s++) {
        const uint2 u = ((const uint2*)g_scr[s])[i];
        const __half2 p0 = *reinterpret_cast<const __half2*>(&u.x);
        const __half2 p1 = *reinterpret_cast<const __half2*>(&u.y);
        a.x += __low2float(p0);  a.y += __high2float(p0);
        a.z += __low2float(p1);  a.w += __high2float(p1);
        l += g_l[s][row];
    }
    const float inv = 1.0f / l;
    ((float4*)O)[i] = make_float4(a.x * inv, a.y * inv, a.z * inv, a.w * inv);
}

extern "C" void kernel_launch(void* const* d_in, const int* in_sizes, int n_in,
                              void* d_out, int out_size) {
    const float* Q      = (const float*)d_in[0];
    const float* K      = (const float*)d_in[1];
    const float* V      = (const float*)d_in[2];
    const int*   prefix = (const int*)d_in[3];
    float*       O      = (float*)d_out;

    prep_kernel<<<dim3(32, 8), 256>>>(K, V);
    cudaFuncSetAttribute(attn_part_kernel,
                         cudaFuncAttributeMaxDynamicSharedMemorySize, SM_TOTAL);
    attn_part_kernel<<<dim3(16, 8, KS), 256, SM_TOTAL>>>(Q, prefix);
    combine_kernel<<<(8 * SEQ * DH / 4) / 256, 256>>>(O);
}